// round 3
// baseline (speedup 1.0000x reference)
#include <cuda_runtime.h>
#include <cuda_bf16.h>

// VanillaRNN: diagonal recurrence h <- tanh(x_t * w_in + h * w_diag + b_h),
// then out = h_final @ W_hp^T + b_o.
// ILP=2: each thread owns hidden units h and h+128 of one batch row, sharing
// the xs[t] broadcast load between the two independent MUFU chains.

#define RB 1024   // batch
#define RT 1024   // time steps
#define RH 256    // hidden
#define RC 10     // classes
#define TPB 128   // threads per block (each handles 2 hidden units)

__device__ __forceinline__ float tanh_hw(float x) {
    float r;
    asm("tanh.approx.f32 %0, %1;" : "=f"(r) : "f"(x));
    return r;
}

__global__ __launch_bounds__(TPB, 16)
void vanilla_rnn_kernel(const float* __restrict__ x,
                        const float* __restrict__ W_hx,
                        const float* __restrict__ W_hh,
                        const float* __restrict__ b_h,
                        const float* __restrict__ W_hp,
                        const float* __restrict__ b_o,
                        float* __restrict__ out)
{
    __shared__ float xs[RT];     // this block's x row (4 KB)
    __shared__ float hs[RH];     // final hidden state for epilogue

    const int b  = blockIdx.x;
    const int h0 = threadIdx.x;         // first hidden unit
    const int h1 = threadIdx.x + TPB;   // second hidden unit

    // Stage x[b, :]: 128 threads x 2 float4 = 1024 floats.
    {
        const float4* xrow = reinterpret_cast<const float4*>(x + (size_t)b * RT);
        float4* xsv = reinterpret_cast<float4*>(xs);
        xsv[h0]       = xrow[h0];
        xsv[h0 + TPB] = xrow[h0 + TPB];
    }

    const float wi0 = W_hx[h0];
    const float wi1 = W_hx[h1];
    const float wd0 = W_hh[h0 * RH + h0];
    const float wd1 = W_hh[h1 * RH + h1];
    const float bh0 = b_h[h0];
    const float bh1 = b_h[h1];

    __syncthreads();

    float hv0 = 0.0f, hv1 = 0.0f;
    #pragma unroll 16
    for (int t = 0; t < RT; t++) {
        const float xt = xs[t];
        float z0 = fmaf(xt, wi0, fmaf(hv0, wd0, bh0));
        float z1 = fmaf(xt, wi1, fmaf(hv1, wd1, bh1));
        hv0 = tanh_hw(z0);
        hv1 = tanh_hw(z1);
    }

    hs[h0] = hv0;
    hs[h1] = hv1;
    __syncthreads();

    // Epilogue: out[b, c] = sum_h hs[h] * W_hp[c, h] + b_o[c]
    if (h0 < RC) {
        const float* wrow = W_hp + h0 * RH;
        float acc = b_o[h0];
        #pragma unroll 8
        for (int j = 0; j < RH; j++)
            acc = fmaf(hs[j], wrow[j], acc);
        out[b * RC + h0] = acc;
    }
}

extern "C" void kernel_launch(void* const* d_in, const int* in_sizes, int n_in,
                              void* d_out, int out_size)
{
    const float* x    = (const float*)d_in[0];
    const float* W_hx = (const float*)d_in[1];
    const float* W_hh = (const float*)d_in[2];
    const float* b_h  = (const float*)d_in[3];
    const float* W_hp = (const float*)d_in[4];
    const float* b_o  = (const float*)d_in[5];
    float* out = (float*)d_out;

    vanilla_rnn_kernel<<<RB, TPB>>>(x, W_hx, W_hh, b_h, W_hp, b_o, out);
}

// round 5
// speedup vs baseline: 1.6624x; 1.6624x over previous
#include <cuda_runtime.h>
#include <cuda_bf16.h>

// VanillaRNN diagonal recurrence, f32 (f16 state variants proven numerically
// fatal in R4: recurrence is marginally stable, amp ~14x).
// Key change vs R2: re-associate the affine so the loop-carried chain is
// only  FFMA(hv*wd + a_t) -> MUFU.TANH ; a_t = x_t*wi + bh is t-only and
// hoists off the critical path. x staged via float4 (LDS.128 per 4 iters).

#define RB 1024   // batch
#define RT 1024   // time steps
#define RH 256    // hidden
#define RC 10     // classes

__device__ __forceinline__ float tanh_hw(float x) {
    float r;
    asm("tanh.approx.f32 %0, %1;" : "=f"(r) : "f"(x));
    return r;
}

__global__ __launch_bounds__(RH, 8)
void vanilla_rnn_kernel(const float* __restrict__ x,
                        const float* __restrict__ W_hx,
                        const float* __restrict__ W_hh,
                        const float* __restrict__ b_h,
                        const float* __restrict__ W_hp,
                        const float* __restrict__ b_o,
                        float* __restrict__ out)
{
    __shared__ float4 xs4[RT / 4];   // this block's x row (4 KB), float4-packed
    __shared__ float  hs[RH];        // final hidden state for epilogue

    const int b = blockIdx.x;
    const int h = threadIdx.x;

    // Stage x[b, :]: 256 threads x 1 float4 = 1024 floats.
    {
        const float4* xrow = reinterpret_cast<const float4*>(x + (size_t)b * RT);
        xs4[h] = xrow[h];
    }

    const float wi = W_hx[h];           // W_hx[h, 0]
    const float wd = W_hh[h * RH + h];  // diag(W_hh)[h]
    const float bh = b_h[h];

    __syncthreads();

    float hv = 0.0f;
    #pragma unroll 4
    for (int q = 0; q < RT / 4; q++) {
        float4 xv = xs4[q];
        // a_* are t-only: computed off the loop-carried chain.
        float a0 = fmaf(xv.x, wi, bh);
        float a1 = fmaf(xv.y, wi, bh);
        float a2 = fmaf(xv.z, wi, bh);
        float a3 = fmaf(xv.w, wi, bh);
        hv = tanh_hw(fmaf(hv, wd, a0));
        hv = tanh_hw(fmaf(hv, wd, a1));
        hv = tanh_hw(fmaf(hv, wd, a2));
        hv = tanh_hw(fmaf(hv, wd, a3));
    }

    hs[h] = hv;
    __syncthreads();

    // Epilogue: out[b, c] = sum_h hs[h] * W_hp[c, h] + b_o[c]
    if (h < RC) {
        const float* wrow = W_hp + h * RH;
        float acc = b_o[h];
        #pragma unroll 8
        for (int j = 0; j < RH; j++)
            acc = fmaf(hs[j], wrow[j], acc);
        out[b * RC + h] = acc;
    }
}

extern "C" void kernel_launch(void* const* d_in, const int* in_sizes, int n_in,
                              void* d_out, int out_size)
{
    const float* x    = (const float*)d_in[0];
    const float* W_hx = (const float*)d_in[1];
    const float* W_hh = (const float*)d_in[2];
    const float* b_h  = (const float*)d_in[3];
    const float* W_hp = (const float*)d_in[4];
    const float* b_o  = (const float*)d_in[5];
    float* out = (float*)d_out;

    vanilla_rnn_kernel<<<RB, RH>>>(x, W_hx, W_hh, b_h, W_hp, b_o, out);
}